// round 7
// baseline (speedup 1.0000x reference)
#include <cuda_runtime.h>
#include <math.h>

#define NN 512
#define FF 64
#define SS 5
#define TT 32
#define NC 4      // sender chunks per receiver
#define TSZ 16    // sender tile size
#define SHE 33    // sHe row stride (pad)
#define SWJ 322   // swj row stride (pad)

// -------- device scratch (no allocations allowed) --------
__device__ float g_nf0[NN*FF];
__device__ float g_nf1[NN*3*FF];
__device__ float g_x0[NN*FF];
__device__ float g_x1[NN*3*FF];
__device__ float g_Apart[NC*NN*9*FF];
__device__ float g_pos[NN*3];

// round fp32 -> tf32 bit pattern (returned as float with low mantissa cleared)
__device__ __forceinline__ float tf32f(float x) {
    unsigned r;
    asm("cvt.rna.tf32.f32 %0, %1;" : "=r"(r) : "f"(x));
    return __uint_as_float(r);
}

// m16n8k8 tf32 MMA: D += A(16x8) * B(8x8)
__device__ __forceinline__ void mma_tf32(float& d0, float& d1, float& d2, float& d3,
                                         unsigned a0, unsigned a1, unsigned a2, unsigned a3,
                                         unsigned b0, unsigned b1) {
    asm volatile(
        "mma.sync.aligned.m16n8k8.row.col.f32.tf32.tf32.f32 "
        "{%0,%1,%2,%3}, {%4,%5,%6,%7}, {%8,%9}, {%0,%1,%2,%3};\n"
        : "+f"(d0), "+f"(d1), "+f"(d2), "+f"(d3)
        : "r"(a0), "r"(a1), "r"(a2), "r"(a3), "r"(b0), "r"(b1));
}

// -------- embed --------
__global__ void k_embed(const float* __restrict__ pos_in, const int* __restrict__ nodef,
                        const float* __restrict__ te, const float* __restrict__ W_embed,
                        const float* __restrict__ b_embed) {
    int n = blockIdx.x, f = threadIdx.x;
    if (f < 3) g_pos[n*3+f] = pos_in[n*3+f];
    int sp = nodef[n] - 1;
    float h = W_embed[sp*FF + f] + b_embed[f];
    #pragma unroll
    for (int t = 0; t < TT; t++) h = fmaf(te[t], W_embed[(SS+t)*FF + f], h);
    g_nf0[n*FF + f] = h;
}

// -------- per-layer node linear --------
template<bool FIRST>
__global__ void k_linear(const float* __restrict__ Wlin) {
    __shared__ float s0[FF];
    __shared__ float s1[3][FF];
    int n = blockIdx.x, f = threadIdx.x;
    s0[f] = g_nf0[n*FF + f];
    if (!FIRST) {
        s1[0][f] = g_nf1[(n*3+0)*FF + f];
        s1[1][f] = g_nf1[(n*3+1)*FF + f];
        s1[2][f] = g_nf1[(n*3+2)*FF + f];
    }
    __syncthreads();
    float a0 = 0.f, a1x = 0.f, a1y = 0.f, a1z = 0.f;
    #pragma unroll 8
    for (int g = 0; g < FF; g++) {
        float w0 = Wlin[g*FF + f];
        a0 = fmaf(s0[g], w0, a0);
        if (!FIRST) {
            float w1 = Wlin[FF*FF + g*FF + f];
            a1x = fmaf(s1[0][g], w1, a1x);
            a1y = fmaf(s1[1][g], w1, a1y);
            a1z = fmaf(s1[2][g], w1, a1z);
        }
    }
    g_x0[n*FF + f] = a0;
    if (!FIRST) {
        g_x1[(n*3+0)*FF + f] = a1x;
        g_x1[(n*3+1)*FF + f] = a1y;
        g_x1[(n*3+2)*FF + f] = a1z;
    }
}

// -------- edge kernel: wj via tensor-core tf32 MMA, epilogue scalar --------
// NJ = 3 (layer 0, s1==0) or 5 (layer 1). j==5 never needed.
template<int NJ>
__global__ void __launch_bounds__(64) k_edge(const float* __restrict__ We1,
                                             const float* __restrict__ be1,
                                             const float* __restrict__ We2) {
    constexpr int NT  = NJ * FF / 8;   // n-tiles of 8 (24 or 40)
    constexpr int NTW = NT / 2;        // n-tiles per warp (12 or 20)

    const int c = blockIdx.x, r = blockIdx.y, f = threadIdx.x;
    const int w = f >> 5, lane = f & 31;
    const int gq = lane >> 2, tg = lane & 3;   // fragment row-group / thread-in-group

    __shared__ float sWe1[32], sBe1[32];
    __shared__ float sY1[TSZ][3];
    __shared__ float sY2[TSZ][5];
    __shared__ float sRl[TSZ];
    __shared__ float sVal[TSZ];
    __shared__ float sHe[TSZ*SHE];     // tf32-rounded silu features
    __shared__ float swj[TSZ*SWJ];     // wj tile [sl][f*NJ+j]

    if (f < 32) { sWe1[f] = We1[f]; sBe1[f] = be1[f]; }
    const float prx = g_pos[r*3+0], pry = g_pos[r*3+1], prz = g_pos[r*3+2];

    // B fragments (static We2, tf32) in registers, once per block.
    // b0: k = kt*8+tg, b1: k = kt*8+tg+4, n = nt*8+gq ; n -> (f'=n/NJ, j=n%NJ) -> col f'*6+j
    float2 Breg[NTW][4];
    #pragma unroll
    for (int ntl = 0; ntl < NTW; ntl++) {
        int n = (w*NTW + ntl)*8 + gq;
        int col = (n / NJ)*6 + (n % NJ);
        #pragma unroll
        for (int kt = 0; kt < 4; kt++) {
            int k0 = kt*8 + tg;
            Breg[ntl][kt].x = tf32f(We2[k0*384 + col]);
            Breg[ntl][kt].y = tf32f(We2[(k0+4)*384 + col]);
        }
    }

    float acc[9];
    #pragma unroll
    for (int ch = 0; ch < 9; ch++) acc[ch] = 0.f;

    const int base = c * (NN/NC);
    for (int tile = 0; tile < (NN/NC)/TSZ; tile++) {
        __syncthreads();
        if (f < TSZ) {
            int s = base + tile*TSZ + f;
            float vx = prx - g_pos[s*3+0];
            float vy = pry - g_pos[s*3+1];
            float vz = prz - g_pos[s*3+2];
            float rl = sqrtf(vx*vx + vy*vy + vz*vz);
            int ok = (s != r);
            float inv = ok ? (1.0f/rl) : 0.0f;
            float ux = vx*inv, uy = vy*inv, uz = vz*inv;
            sRl[f] = rl;
            sVal[f] = ok ? 1.0f : 0.0f;
            const float s3  = 1.7320508075688772f;
            const float s5h = 0.5f * 2.2360679774997896f;
            const float s15 = 3.8729833462074170f;
            const float s15h = 0.5f * 3.8729833462074170f;
            sY1[f][0] = s3*ux; sY1[f][1] = s3*uy; sY1[f][2] = s3*uz;
            sY2[f][0] = s15*ux*uy;
            sY2[f][1] = s15*uy*uz;
            sY2[f][2] = s5h*(3.f*uz*uz - 1.f);
            sY2[f][3] = s15*ux*uz;
            sY2[f][4] = s15h*(ux*ux - uy*uy);
        }
        __syncthreads();
        // he = silu(r*We1+be1) masked, tf32-rounded for the MMA
        #pragma unroll
        for (int i = 0; i < (TSZ*32)/64; i++) {
            int idx = i*64 + f; int sl = idx >> 5, k = idx & 31;
            float x = fmaf(sRl[sl], sWe1[k], sBe1[k]);
            sHe[sl*SHE + k] = tf32f((x / (1.0f + expf(-x))) * sVal[sl]);
        }
        __syncthreads();

        // ---- GEMM phase: wj[16, FF*NJ] = He[16,32] @ We2'[32, FF*NJ] ----
        unsigned a[4][4];
        #pragma unroll
        for (int kt = 0; kt < 4; kt++) {
            a[kt][0] = __float_as_uint(sHe[ gq     *SHE + kt*8 + tg    ]);
            a[kt][1] = __float_as_uint(sHe[(gq+8)  *SHE + kt*8 + tg    ]);
            a[kt][2] = __float_as_uint(sHe[ gq     *SHE + kt*8 + tg + 4]);
            a[kt][3] = __float_as_uint(sHe[(gq+8)  *SHE + kt*8 + tg + 4]);
        }
        #pragma unroll
        for (int ntl = 0; ntl < NTW; ntl++) {
            float d0 = 0.f, d1 = 0.f, d2 = 0.f, d3 = 0.f;
            #pragma unroll
            for (int kt = 0; kt < 4; kt++)
                mma_tf32(d0, d1, d2, d3,
                         a[kt][0], a[kt][1], a[kt][2], a[kt][3],
                         __float_as_uint(Breg[ntl][kt].x),
                         __float_as_uint(Breg[ntl][kt].y));
            int nbase = (w*NTW + ntl)*8 + 2*tg;
            swj[ gq   *SWJ + nbase    ] = d0;
            swj[ gq   *SWJ + nbase + 1] = d1;
            swj[(gq+8)*SWJ + nbase    ] = d2;
            swj[(gq+8)*SWJ + nbase + 1] = d3;
        }
        __syncthreads();

        // ---- epilogue: messages, per (sl, f) ----
        #pragma unroll 1
        for (int sl = 0; sl < TSZ; sl++) {
            int s = base + tile*TSZ + sl;
            float a0v = g_x0[s*FF + f];
            float a1x = 0.f, a1y = 0.f, a1z = 0.f;
            if (NJ > 3) {
                a1x = g_x1[(s*3+0)*FF + f];
                a1y = g_x1[(s*3+1)*FF + f];
                a1z = g_x1[(s*3+2)*FF + f];
            }
            float wj[NJ];
            #pragma unroll
            for (int j = 0; j < NJ; j++) wj[j] = swj[sl*SWJ + f*NJ + j];

            float Y1x = sY1[sl][0], Y1y = sY1[sl][1], Y1z = sY1[sl][2];
            acc[0] = fmaf(wj[0], a0v, acc[0]);
            float w1a = wj[1] * a0v;
            acc[1] = fmaf(w1a, Y1x, acc[1]);
            acc[2] = fmaf(w1a, Y1y, acc[2]);
            acc[3] = fmaf(w1a, Y1z, acc[3]);
            float w2a = wj[2] * a0v;
            acc[4] = fmaf(w2a, sY2[sl][0], acc[4]);
            acc[5] = fmaf(w2a, sY2[sl][1], acc[5]);
            acc[6] = fmaf(w2a, sY2[sl][2], acc[6]);
            acc[7] = fmaf(w2a, sY2[sl][3], acc[7]);
            acc[8] = fmaf(w2a, sY2[sl][4], acc[8]);
            if (NJ > 3) {
                float d1v = a1x*Y1x + a1y*Y1y + a1z*Y1z;
                acc[0] = fmaf(wj[3], d1v, acc[0]);
                float crx = a1y*Y1z - a1z*Y1y;
                float cry = a1z*Y1x - a1x*Y1z;
                float crz = a1x*Y1y - a1y*Y1x;
                acc[1] = fmaf(wj[4], crx, acc[1]);
                acc[2] = fmaf(wj[4], cry, acc[2]);
                acc[3] = fmaf(wj[4], crz, acc[3]);
            }
        }
    }
    #pragma unroll
    for (int ch = 0; ch < 9; ch++)
        g_Apart[((c*NN + r)*9 + ch)*FF + f] = acc[ch];
}

// -------- node update --------
__global__ void k_node(const int* __restrict__ nodef,
                       const float* __restrict__ Wp0, const float* __restrict__ Wp1,
                       const float* __restrict__ Wr1, const float* __restrict__ br1,
                       const float* __restrict__ Wr2g) {
    int n = blockIdx.x, f = threadIdx.x;
    float A[9];
    #pragma unroll
    for (int ch = 0; ch < 9; ch++) {
        float s = 0.f;
        #pragma unroll
        for (int c = 0; c < NC; c++) s += g_Apart[((c*NN + n)*9 + ch)*FF + f];
        A[ch] = s / 511.0f;
    }
    float A0 = A[0];
    float n1 = A[1]*A[1] + A[2]*A[2] + A[3]*A[3];
    float n2 = A[4]*A[4] + A[5]*A[5] + A[6]*A[6] + A[7]*A[7] + A[8]*A[8];
    int sp = nodef[n] - 1;
    const float* w0 = Wp0 + (sp*FF + f)*6;
    float A02 = A0*A0;
    float out0 = w0[0]*A0 + w0[1]*A02 + w0[2]*A02*A0 + w0[3]*n1 + w0[4]*n2 + w0[5]*A0*n1;
    const float* w1 = Wp1 + (sp*FF + f)*3;
    float gp = w1[0] + w1[1]*A0 + w1[2]*A02;
    float o1x = gp*A[1], o1y = gp*A[2], o1z = gp*A[3];
    g_nf0[n*FF + f] = out0;
    g_nf1[(n*3+0)*FF + f] = o1x;
    g_nf1[(n*3+1)*FF + f] = o1y;
    g_nf1[(n*3+2)*FF + f] = o1z;

    __shared__ float sO[FF];
    sO[f] = out0;
    __syncthreads();
    float hx = br1[f];
    #pragma unroll 8
    for (int g = 0; g < FF; g++) hx = fmaf(sO[g], Wr1[g*FF + f], hx);
    float hr = hx / (1.0f + expf(-hx));
    __shared__ float sH[FF];
    sH[f] = hr;
    __syncthreads();
    float gate = 0.f;
    #pragma unroll 8
    for (int m = 0; m < FF; m++) gate = fmaf(sH[m], Wr2g[m*FF + f], gate);

    __shared__ float sRed[3][FF];
    sRed[0][f] = gate*o1x; sRed[1][f] = gate*o1y; sRed[2][f] = gate*o1z;
    __syncthreads();
    if (f < 3) {
        float v = 0.f;
        for (int g = 0; g < FF; g++) v += sRed[f][g];
        g_pos[n*3 + f] += v;
    }
}

__global__ void k_out(const float* __restrict__ pos_in, float* __restrict__ out) {
    int i = blockIdx.x*blockDim.x + threadIdx.x;
    if (i < NN*3) out[i] = g_pos[i] - pos_in[i];
}

extern "C" void kernel_launch(void* const* d_in, const int* in_sizes, int n_in,
                              void* d_out, int out_size) {
    const float* positions = (const float*)d_in[0];
    const int*   nodef     = (const int*)  d_in[1];
    const float* te        = (const float*)d_in[2];
    const float* W_embed   = (const float*)d_in[5];
    const float* b_embed   = (const float*)d_in[6];
    const float* W_lin     = (const float*)d_in[7];
    const float* W_e1      = (const float*)d_in[8];
    const float* b_e1      = (const float*)d_in[9];
    const float* W_e2      = (const float*)d_in[10];
    const float* Wp0       = (const float*)d_in[11];
    const float* Wp1       = (const float*)d_in[12];
    const float* Wr1       = (const float*)d_in[13];
    const float* br1       = (const float*)d_in[14];
    const float* Wr2g      = (const float*)d_in[16];
    float* out = (float*)d_out;

    k_embed<<<NN, FF>>>(positions, nodef, te, W_embed, b_embed);

    // layer 0
    k_linear<true><<<NN, FF>>>(W_lin);
    k_edge<3><<<dim3(NC, NN), 64>>>(W_e1, b_e1, W_e2);
    k_node<<<NN, FF>>>(nodef, Wp0, Wp1, Wr1, br1, Wr2g);

    // layer 1
    k_linear<false><<<NN, FF>>>(W_lin + 3*FF*FF);
    k_edge<5><<<dim3(NC, NN), 64>>>(W_e1 + 32, b_e1 + 32, W_e2 + 32*384);
    k_node<<<NN, FF>>>(nodef, Wp0 + SS*FF*6, Wp1 + SS*FF*3, Wr1 + FF*FF, br1 + FF, Wr2g + FF*FF);

    k_out<<<(NN*3 + 255)/256, 256>>>(positions, out);
}

// round 8
// speedup vs baseline: 1.9843x; 1.9843x over previous
#include <cuda_runtime.h>
#include <math.h>

#define NN 512
#define FF 64
#define SS 5
#define TT 32
#define NC 4       // sender chunks per receiver
#define TSZ 16     // sender tile size
#define NPTS 8192  // wj table points
#define RMAX 16.0f

// -------- device scratch (no allocations allowed) --------
__device__ float4 g_xv[NN*FF];          // per (node, f): {x0, x1x, x1y, x1z}
__device__ float4 g_tab4[NPTS*FF];      // wj table, j=0..3 (j=3 pad for layer0)
__device__ float  g_tabE[NPTS*FF];      // wj table, j=4 (layer1 only)
__device__ float  g_Apart[NC*NN*9*FF];  // partial segment sums
__device__ float  g_pos[NN*3];          // current positions

// -------- fused embed + layer0 linear --------
__global__ void k_embedlin(const float* __restrict__ pos_in, const int* __restrict__ nodef,
                           const float* __restrict__ te, const float* __restrict__ W_embed,
                           const float* __restrict__ b_embed, const float* __restrict__ Wl0) {
    int n = blockIdx.x, f = threadIdx.x;
    __shared__ float sH[FF];
    if (f < 3) g_pos[n*3+f] = pos_in[n*3+f];
    int sp = nodef[n] - 1;
    float h = W_embed[sp*FF + f] + b_embed[f];
    #pragma unroll
    for (int t = 0; t < TT; t++) h = fmaf(te[t], W_embed[(SS+t)*FF + f], h);
    sH[f] = h;
    __syncthreads();
    float a0 = 0.f;
    #pragma unroll 8
    for (int g = 0; g < FF; g++) a0 = fmaf(sH[g], Wl0[g*FF + f], a0);
    g_xv[n*FF + f] = make_float4(a0, 0.f, 0.f, 0.f);
}

// -------- build wj(r) table for one layer --------
// col mapping: j-th output for feature f lives at We2 column f*6+j.
template<int NJ>
__global__ void k_tab(const float* __restrict__ We1, const float* __restrict__ be1,
                      const float* __restrict__ We2) {
    int p = blockIdx.x, f = threadIdx.x;
    __shared__ float he[32];
    if (f < 32) {
        float r = (float)p * (RMAX / (float)(NPTS-1));
        float x = fmaf(r, We1[f], be1[f]);
        he[f] = x / (1.0f + expf(-x));
    }
    __syncthreads();
    float4 v = make_float4(0.f, 0.f, 0.f, 0.f);
    float e = 0.f;
    #pragma unroll 8
    for (int k = 0; k < 32; k++) {
        float h = he[k];
        const float* w = We2 + k*384 + f*6;
        v.x = fmaf(h, w[0], v.x);
        v.y = fmaf(h, w[1], v.y);
        v.z = fmaf(h, w[2], v.z);
        if (NJ > 3) {
            v.w = fmaf(h, w[3], v.w);
            e   = fmaf(h, w[4], e);
        }
    }
    g_tab4[p*FF + f] = v;
    if (NJ > 3) g_tabE[p*FF + f] = e;
}

// -------- edge kernel: table-lookup wj + message epilogue --------
// NJ = 3 (layer 0, s1==0) or 5 (layer 1). j==5 term is identically zero.
template<int NJ>
__global__ void __launch_bounds__(64) k_edge() {
    const int c = blockIdx.x, r = blockIdx.y, f = threadIdx.x;
    __shared__ float sY1[TSZ][3];
    __shared__ float sY2[TSZ][5];
    __shared__ int   sIdx[TSZ];
    __shared__ float sFrac[TSZ];
    __shared__ float sVal[TSZ];

    const float prx = g_pos[r*3+0], pry = g_pos[r*3+1], prz = g_pos[r*3+2];
    const float tscale = (float)(NPTS-1) / RMAX;

    float acc[9];
    #pragma unroll
    for (int ch = 0; ch < 9; ch++) acc[ch] = 0.f;

    const int base = c * (NN/NC);
    for (int tile = 0; tile < (NN/NC)/TSZ; tile++) {
        __syncthreads();
        if (f < TSZ) {
            int s = base + tile*TSZ + f;
            float vx = prx - g_pos[s*3+0];
            float vy = pry - g_pos[s*3+1];
            float vz = prz - g_pos[s*3+2];
            float rl = sqrtf(vx*vx + vy*vy + vz*vz);
            int ok = (s != r);
            float inv = ok ? (1.0f/rl) : 0.0f;
            float ux = vx*inv, uy = vy*inv, uz = vz*inv;
            float t = fminf(rl * tscale, (float)NPTS - 1.001f);
            int i = (int)t;
            sIdx[f]  = i;
            sFrac[f] = t - (float)i;
            sVal[f]  = ok ? 1.0f : 0.0f;
            const float s3  = 1.7320508075688772f;
            const float s5h = 0.5f * 2.2360679774997896f;
            const float s15 = 3.8729833462074170f;
            const float s15h = 0.5f * 3.8729833462074170f;
            sY1[f][0] = s3*ux; sY1[f][1] = s3*uy; sY1[f][2] = s3*uz;
            sY2[f][0] = s15*ux*uy;
            sY2[f][1] = s15*uy*uz;
            sY2[f][2] = s5h*(3.f*uz*uz - 1.f);
            sY2[f][3] = s15*ux*uz;
            sY2[f][4] = s15h*(ux*ux - uy*uy);
        }
        __syncthreads();
        #pragma unroll 1
        for (int sl = 0; sl < TSZ; sl++) {
            int s = base + tile*TSZ + sl;
            int i = sIdx[sl];
            float fr = sFrac[sl], val = sVal[sl];

            float4 Ta = g_tab4[i*FF + f];
            float4 Tb = g_tab4[(i+1)*FF + f];
            float wj0 = fmaf(fr, Tb.x - Ta.x, Ta.x);
            float wj1 = fmaf(fr, Tb.y - Ta.y, Ta.y);
            float wj2 = fmaf(fr, Tb.z - Ta.z, Ta.z);
            float wj3 = 0.f, wj4 = 0.f;
            if (NJ > 3) {
                wj3 = fmaf(fr, Tb.w - Ta.w, Ta.w);
                float ea = g_tabE[i*FF + f], eb = g_tabE[(i+1)*FF + f];
                wj4 = fmaf(fr, eb - ea, ea);
            }

            float4 xv = g_xv[s*FF + f];
            float a0v = xv.x * val;
            float Y1x = sY1[sl][0], Y1y = sY1[sl][1], Y1z = sY1[sl][2];

            acc[0] = fmaf(wj0, a0v, acc[0]);
            float w1a = wj1 * a0v;
            acc[1] = fmaf(w1a, Y1x, acc[1]);
            acc[2] = fmaf(w1a, Y1y, acc[2]);
            acc[3] = fmaf(w1a, Y1z, acc[3]);
            float w2a = wj2 * a0v;
            acc[4] = fmaf(w2a, sY2[sl][0], acc[4]);
            acc[5] = fmaf(w2a, sY2[sl][1], acc[5]);
            acc[6] = fmaf(w2a, sY2[sl][2], acc[6]);
            acc[7] = fmaf(w2a, sY2[sl][3], acc[7]);
            acc[8] = fmaf(w2a, sY2[sl][4], acc[8]);
            if (NJ > 3) {
                float a1x = xv.y * val, a1y = xv.z * val, a1z = xv.w * val;
                float d1 = a1x*Y1x + a1y*Y1y + a1z*Y1z;
                acc[0] = fmaf(wj3, d1, acc[0]);
                float crx = a1y*Y1z - a1z*Y1y;
                float cry = a1z*Y1x - a1x*Y1z;
                float crz = a1x*Y1y - a1y*Y1x;
                acc[1] = fmaf(wj4, crx, acc[1]);
                acc[2] = fmaf(wj4, cry, acc[2]);
                acc[3] = fmaf(wj4, crz, acc[3]);
            }
        }
    }
    #pragma unroll
    for (int ch = 0; ch < 9; ch++)
        g_Apart[((c*NN + r)*9 + ch)*FF + f] = acc[ch];
}

// -------- node update: reduce, nonlinearity, readout, pos +=, next-layer linear --------
template<bool DO_LIN>
__global__ void k_node(const int* __restrict__ nodef,
                       const float* __restrict__ Wp0, const float* __restrict__ Wp1,
                       const float* __restrict__ Wr1, const float* __restrict__ br1,
                       const float* __restrict__ Wr2g, const float* __restrict__ WlinNext) {
    int n = blockIdx.x, f = threadIdx.x;
    float A[9];
    #pragma unroll
    for (int ch = 0; ch < 9; ch++) {
        float s = 0.f;
        #pragma unroll
        for (int c = 0; c < NC; c++) s += g_Apart[((c*NN + n)*9 + ch)*FF + f];
        A[ch] = s / 511.0f;
    }
    float A0 = A[0];
    float n1 = A[1]*A[1] + A[2]*A[2] + A[3]*A[3];
    float n2 = A[4]*A[4] + A[5]*A[5] + A[6]*A[6] + A[7]*A[7] + A[8]*A[8];
    int sp = nodef[n] - 1;
    const float* w0 = Wp0 + (sp*FF + f)*6;
    float A02 = A0*A0;
    float out0 = w0[0]*A0 + w0[1]*A02 + w0[2]*A02*A0 + w0[3]*n1 + w0[4]*n2 + w0[5]*A0*n1;
    const float* w1 = Wp1 + (sp*FF + f)*3;
    float gp = w1[0] + w1[1]*A0 + w1[2]*A02;
    float o1x = gp*A[1], o1y = gp*A[2], o1z = gp*A[3];

    __shared__ float sO[FF];
    __shared__ float sV[3][FF];
    sO[f] = out0;
    sV[0][f] = o1x; sV[1][f] = o1y; sV[2][f] = o1z;
    __syncthreads();

    if (DO_LIN) {
        float a0 = 0.f, a1x = 0.f, a1y = 0.f, a1z = 0.f;
        #pragma unroll 8
        for (int g = 0; g < FF; g++) {
            float wa = WlinNext[g*FF + f];
            float wb = WlinNext[FF*FF + g*FF + f];
            a0  = fmaf(sO[g],    wa, a0);
            a1x = fmaf(sV[0][g], wb, a1x);
            a1y = fmaf(sV[1][g], wb, a1y);
            a1z = fmaf(sV[2][g], wb, a1z);
        }
        g_xv[n*FF + f] = make_float4(a0, a1x, a1y, a1z);
    }

    float hx = br1[f];
    #pragma unroll 8
    for (int g = 0; g < FF; g++) hx = fmaf(sO[g], Wr1[g*FF + f], hx);
    float hr = hx / (1.0f + expf(-hx));
    __shared__ float sH[FF];
    sH[f] = hr;
    __syncthreads();
    float gate = 0.f;
    #pragma unroll 8
    for (int m = 0; m < FF; m++) gate = fmaf(sH[m], Wr2g[m*FF + f], gate);

    __shared__ float sRed[3][FF];
    sRed[0][f] = gate*o1x; sRed[1][f] = gate*o1y; sRed[2][f] = gate*o1z;
    __syncthreads();
    if (f < 3) {
        float v = 0.f;
        for (int g = 0; g < FF; g++) v += sRed[f][g];
        g_pos[n*3 + f] += v;   // deterministic: one thread per component
    }
}

__global__ void k_out(const float* __restrict__ pos_in, float* __restrict__ out) {
    int i = blockIdx.x*blockDim.x + threadIdx.x;
    if (i < NN*3) out[i] = g_pos[i] - pos_in[i];
}

extern "C" void kernel_launch(void* const* d_in, const int* in_sizes, int n_in,
                              void* d_out, int out_size) {
    const float* positions = (const float*)d_in[0];
    const int*   nodef     = (const int*)  d_in[1];
    const float* te        = (const float*)d_in[2];
    // d_in[3]/[4] = senders/receivers: fully connected, structure used directly
    const float* W_embed   = (const float*)d_in[5];
    const float* b_embed   = (const float*)d_in[6];
    const float* W_lin     = (const float*)d_in[7];
    const float* W_e1      = (const float*)d_in[8];
    const float* b_e1      = (const float*)d_in[9];
    const float* W_e2      = (const float*)d_in[10];
    const float* Wp0       = (const float*)d_in[11];
    const float* Wp1       = (const float*)d_in[12];
    const float* Wr1       = (const float*)d_in[13];
    const float* br1       = (const float*)d_in[14];
    // d_in[15] = Wr2s: unused by the reference
    const float* Wr2g      = (const float*)d_in[16];
    float* out = (float*)d_out;

    k_embedlin<<<NN, FF>>>(positions, nodef, te, W_embed, b_embed, W_lin);

    // layer 0 (s1 == 0 -> only j in {0,1,2})
    k_tab<3><<<NPTS, FF>>>(W_e1, b_e1, W_e2);
    k_edge<3><<<dim3(NC, NN), 64>>>();
    k_node<true><<<NN, FF>>>(nodef, Wp0, Wp1, Wr1, br1, Wr2g, W_lin + 3*FF*FF);

    // layer 1 (j in {0..4}; j==5 multiplies an identically-zero term)
    k_tab<5><<<NPTS, FF>>>(W_e1 + 32, b_e1 + 32, W_e2 + 32*384);
    k_edge<5><<<dim3(NC, NN), 64>>>();
    k_node<false><<<NN, FF>>>(nodef, Wp0 + SS*FF*6, Wp1 + SS*FF*3,
                              Wr1 + FF*FF, br1 + FF, Wr2g + FF*FF, nullptr);

    k_out<<<(NN*3 + 255)/256, 256>>>(positions, out);
}

// round 9
// speedup vs baseline: 2.5552x; 1.2877x over previous
#include <cuda_runtime.h>
#include <cuda_fp16.h>
#include <math.h>

#define NN 512
#define FF 64
#define SS 5
#define TT 32
#define NC 8        // sender chunks per receiver
#define CHUNK (NN/NC)
#define TSZ 16      // sender tile size
#define NPTS 4096   // wj table points
#define RMAX 16.0f

// -------- device scratch (no allocations allowed) --------
__device__ float  g_x0v[NN*FF];          // layer0: x0 only
__device__ float4 g_xv[NN*FF];           // layer1: {x0, x1x, x1y, x1z}
__device__ float4 g_tV[2*NPTS*FF];       // table values v0..v3
__device__ uint2  g_tS[2*NPTS*FF];       // slopes s0..s3 as 2x half2
__device__ float2 g_tE[2*NPTS*FF];       // {v4, s4}  (layer1)
__device__ float  g_Apart[NC*NN*9*FF];   // partial segment sums
__device__ float  g_pos[NN*3];           // current positions

// -------- fused embed + layer0 linear (4 nodes / block) --------
__global__ void k_embedlin(const float* __restrict__ pos_in, const int* __restrict__ nodef,
                           const float* __restrict__ te, const float* __restrict__ W_embed,
                           const float* __restrict__ b_embed, const float* __restrict__ Wl0) {
    int ty = threadIdx.y, f = threadIdx.x;
    int n = blockIdx.x*4 + ty;
    __shared__ float sH[4][FF];
    if (f < 3) g_pos[n*3+f] = pos_in[n*3+f];
    int sp = nodef[n] - 1;
    float h = W_embed[sp*FF + f] + b_embed[f];
    #pragma unroll
    for (int t = 0; t < TT; t++) h = fmaf(te[t], W_embed[(SS+t)*FF + f], h);
    sH[ty][f] = h;
    __syncthreads();
    float a0 = 0.f;
    #pragma unroll 8
    for (int g = 0; g < FF; g++) a0 = fmaf(sH[ty][g], Wl0[g*FF + f], a0);
    g_x0v[n*FF + f] = a0;
}

// -------- build wj(r) table (value + slope), 8 points / block --------
__global__ void k_tab(const float* __restrict__ We1, const float* __restrict__ be1,
                      const float* __restrict__ We2, int off) {
    __shared__ float sW[32*320];    // We2 repacked: [k][f*5+j]
    __shared__ float sHe[9][32];
    int f = threadIdx.x, ty = threadIdx.y;
    int tid = ty*64 + f;
    int p0 = blockIdx.x*8;
    const float hstep = RMAX / (float)(NPTS-1);

    for (int idx = tid; idx < 32*320; idx += 512) {
        int k = idx / 320, cc = idx % 320;
        sW[idx] = We2[k*384 + (cc/5)*6 + (cc%5)];
    }
    for (int idx = tid; idx < 9*32; idx += 512) {
        int row = idx >> 5, k = idx & 31;
        int p = p0 + row; if (p > NPTS-1) p = NPTS-1;
        float x = fmaf((float)p * hstep, We1[k], be1[k]);
        sHe[row][k] = x / (1.0f + expf(-x));
    }
    __syncthreads();

    float va[5] = {0,0,0,0,0}, vb[5] = {0,0,0,0,0};
    #pragma unroll 4
    for (int k = 0; k < 32; k++) {
        float hA = sHe[ty][k], hB = sHe[ty+1][k];
        const float* w = &sW[k*320 + f*5];
        #pragma unroll
        for (int j = 0; j < 5; j++) {
            va[j] = fmaf(hA, w[j], va[j]);
            vb[j] = fmaf(hB, w[j], vb[j]);
        }
    }
    int p = p0 + ty;
    int ti = off + p*FF + f;
    g_tV[ti] = make_float4(va[0], va[1], va[2], va[3]);
    __half2 sa = __floats2half2_rn(vb[0]-va[0], vb[1]-va[1]);
    __half2 sb = __floats2half2_rn(vb[2]-va[2], vb[3]-va[3]);
    uint2 su; su.x = *(unsigned*)&sa; su.y = *(unsigned*)&sb;
    g_tS[ti] = su;
    g_tE[ti] = make_float2(va[4], vb[4]-va[4]);
}

// -------- edge kernel: table lookup + message epilogue --------
// NJ = 3 (layer 0, s1==0) or 5 (layer 1).
template<int NJ>
__global__ void __launch_bounds__(64) k_edge() {
    const int r = blockIdx.x, c = blockIdx.y, f = threadIdx.x;
    const int off = (NJ == 5) ? NPTS*FF : 0;
    __shared__ float sY1[TSZ][3];
    __shared__ float sY2[TSZ][5];
    __shared__ int   sIdx[TSZ];
    __shared__ float sFrac[TSZ];
    __shared__ float sVal[TSZ];

    const float prx = g_pos[r*3+0], pry = g_pos[r*3+1], prz = g_pos[r*3+2];
    const float tscale = (float)(NPTS-1) / RMAX;

    float acc[9];
    #pragma unroll
    for (int ch = 0; ch < 9; ch++) acc[ch] = 0.f;

    const int base = c * CHUNK;
    for (int tile = 0; tile < CHUNK/TSZ; tile++) {
        __syncthreads();
        if (f < TSZ) {
            int s = base + tile*TSZ + f;
            float vx = prx - g_pos[s*3+0];
            float vy = pry - g_pos[s*3+1];
            float vz = prz - g_pos[s*3+2];
            float rl = sqrtf(vx*vx + vy*vy + vz*vz);
            int ok = (s != r);
            float inv = ok ? (1.0f/rl) : 0.0f;
            float ux = vx*inv, uy = vy*inv, uz = vz*inv;
            float t = fminf(rl * tscale, (float)NPTS - 1.001f);
            int i = (int)t;
            sIdx[f]  = i;
            sFrac[f] = t - (float)i;
            sVal[f]  = ok ? 1.0f : 0.0f;
            const float s3  = 1.7320508075688772f;
            const float s5h = 0.5f * 2.2360679774997896f;
            const float s15 = 3.8729833462074170f;
            const float s15h = 0.5f * 3.8729833462074170f;
            sY1[f][0] = s3*ux; sY1[f][1] = s3*uy; sY1[f][2] = s3*uz;
            sY2[f][0] = s15*ux*uy;
            sY2[f][1] = s15*uy*uz;
            sY2[f][2] = s5h*(3.f*uz*uz - 1.f);
            sY2[f][3] = s15*ux*uz;
            sY2[f][4] = s15h*(ux*ux - uy*uy);
        }
        __syncthreads();
        #pragma unroll 4
        for (int sl = 0; sl < TSZ; sl++) {
            int s = base + tile*TSZ + sl;
            int i = sIdx[sl];
            float fr = sFrac[sl], val = sVal[sl];
            int ti = off + i*FF + f;

            float4 V = g_tV[ti];
            uint2 Su = g_tS[ti];
            float2 s01 = __half22float2(*(__half2*)&Su.x);
            float2 s23 = __half22float2(*(__half2*)&Su.y);
            float wj0 = fmaf(fr, s01.x, V.x);
            float wj1 = fmaf(fr, s01.y, V.y);
            float wj2 = fmaf(fr, s23.x, V.z);

            float a0v, a1x = 0.f, a1y = 0.f, a1z = 0.f, wj3 = 0.f, wj4 = 0.f;
            if (NJ > 3) {
                wj3 = fmaf(fr, s23.y, V.w);
                float2 E = g_tE[ti];
                wj4 = fmaf(fr, E.y, E.x);
                float4 xv = g_xv[s*FF + f];
                a0v = xv.x * val;
                a1x = xv.y * val; a1y = xv.z * val; a1z = xv.w * val;
            } else {
                a0v = g_x0v[s*FF + f] * val;
            }

            float Y1x = sY1[sl][0], Y1y = sY1[sl][1], Y1z = sY1[sl][2];
            acc[0] = fmaf(wj0, a0v, acc[0]);
            float w1a = wj1 * a0v;
            acc[1] = fmaf(w1a, Y1x, acc[1]);
            acc[2] = fmaf(w1a, Y1y, acc[2]);
            acc[3] = fmaf(w1a, Y1z, acc[3]);
            float w2a = wj2 * a0v;
            acc[4] = fmaf(w2a, sY2[sl][0], acc[4]);
            acc[5] = fmaf(w2a, sY2[sl][1], acc[5]);
            acc[6] = fmaf(w2a, sY2[sl][2], acc[6]);
            acc[7] = fmaf(w2a, sY2[sl][3], acc[7]);
            acc[8] = fmaf(w2a, sY2[sl][4], acc[8]);
            if (NJ > 3) {
                float d1 = a1x*Y1x + a1y*Y1y + a1z*Y1z;
                acc[0] = fmaf(wj3, d1, acc[0]);
                float crx = a1y*Y1z - a1z*Y1y;
                float cry = a1z*Y1x - a1x*Y1z;
                float crz = a1x*Y1y - a1y*Y1x;
                acc[1] = fmaf(wj4, crx, acc[1]);
                acc[2] = fmaf(wj4, cry, acc[2]);
                acc[3] = fmaf(wj4, crz, acc[3]);
            }
        }
    }
    #pragma unroll
    for (int ch = 0; ch < 9; ch++)
        g_Apart[((c*NN + r)*9 + ch)*FF + f] = acc[ch];
}

// -------- node update (4 nodes / block) --------
template<bool DO_LIN>
__global__ void k_node(const int* __restrict__ nodef,
                       const float* __restrict__ Wp0, const float* __restrict__ Wp1,
                       const float* __restrict__ Wr1, const float* __restrict__ br1,
                       const float* __restrict__ Wr2g, const float* __restrict__ WlinNext) {
    int ty = threadIdx.y, f = threadIdx.x;
    int n = blockIdx.x*4 + ty;
    float A[9];
    #pragma unroll
    for (int ch = 0; ch < 9; ch++) {
        float s = 0.f;
        #pragma unroll
        for (int c = 0; c < NC; c++) s += g_Apart[((c*NN + n)*9 + ch)*FF + f];
        A[ch] = s / 511.0f;
    }
    float A0 = A[0];
    float n1 = A[1]*A[1] + A[2]*A[2] + A[3]*A[3];
    float n2 = A[4]*A[4] + A[5]*A[5] + A[6]*A[6] + A[7]*A[7] + A[8]*A[8];
    int sp = nodef[n] - 1;
    const float* w0 = Wp0 + (sp*FF + f)*6;
    float A02 = A0*A0;
    float out0 = w0[0]*A0 + w0[1]*A02 + w0[2]*A02*A0 + w0[3]*n1 + w0[4]*n2 + w0[5]*A0*n1;
    const float* w1 = Wp1 + (sp*FF + f)*3;
    float gp = w1[0] + w1[1]*A0 + w1[2]*A02;
    float o1x = gp*A[1], o1y = gp*A[2], o1z = gp*A[3];

    __shared__ float sO[4][FF];
    __shared__ float sV[4][3][FF];
    sO[ty][f] = out0;
    sV[ty][0][f] = o1x; sV[ty][1][f] = o1y; sV[ty][2][f] = o1z;
    __syncthreads();

    if (DO_LIN) {
        float a0 = 0.f, a1x = 0.f, a1y = 0.f, a1z = 0.f;
        #pragma unroll 8
        for (int g = 0; g < FF; g++) {
            float wa = WlinNext[g*FF + f];
            float wb = WlinNext[FF*FF + g*FF + f];
            a0  = fmaf(sO[ty][g],    wa, a0);
            a1x = fmaf(sV[ty][0][g], wb, a1x);
            a1y = fmaf(sV[ty][1][g], wb, a1y);
            a1z = fmaf(sV[ty][2][g], wb, a1z);
        }
        g_xv[n*FF + f] = make_float4(a0, a1x, a1y, a1z);
    }

    float hx = br1[f];
    #pragma unroll 8
    for (int g = 0; g < FF; g++) hx = fmaf(sO[ty][g], Wr1[g*FF + f], hx);
    float hr = hx / (1.0f + expf(-hx));
    __shared__ float sH[4][FF];
    sH[ty][f] = hr;
    __syncthreads();
    float gate = 0.f;
    #pragma unroll 8
    for (int m = 0; m < FF; m++) gate = fmaf(sH[ty][m], Wr2g[m*FF + f], gate);

    __shared__ float sRed[4][3][FF];
    sRed[ty][0][f] = gate*o1x; sRed[ty][1][f] = gate*o1y; sRed[ty][2][f] = gate*o1z;
    __syncthreads();
    if (f < 3) {
        float v = 0.f;
        for (int g = 0; g < FF; g++) v += sRed[ty][f][g];
        g_pos[n*3 + f] += v;   // deterministic: one thread per component
    }
}

__global__ void k_out(const float* __restrict__ pos_in, float* __restrict__ out) {
    int i = blockIdx.x*blockDim.x + threadIdx.x;
    if (i < NN*3) out[i] = g_pos[i] - pos_in[i];
}

extern "C" void kernel_launch(void* const* d_in, const int* in_sizes, int n_in,
                              void* d_out, int out_size) {
    const float* positions = (const float*)d_in[0];
    const int*   nodef     = (const int*)  d_in[1];
    const float* te        = (const float*)d_in[2];
    // d_in[3]/[4] = senders/receivers: fully connected, structure used directly
    const float* W_embed   = (const float*)d_in[5];
    const float* b_embed   = (const float*)d_in[6];
    const float* W_lin     = (const float*)d_in[7];
    const float* W_e1      = (const float*)d_in[8];
    const float* b_e1      = (const float*)d_in[9];
    const float* W_e2      = (const float*)d_in[10];
    const float* Wp0       = (const float*)d_in[11];
    const float* Wp1       = (const float*)d_in[12];
    const float* Wr1       = (const float*)d_in[13];
    const float* br1       = (const float*)d_in[14];
    // d_in[15] = Wr2s: unused by the reference
    const float* Wr2g      = (const float*)d_in[16];
    float* out = (float*)d_out;

    dim3 b4(64, 4), b8(64, 8);

    k_embedlin<<<NN/4, b4>>>(positions, nodef, te, W_embed, b_embed, W_lin);
    // both tables up front (independent of edges)
    k_tab<<<NPTS/8, b8>>>(W_e1,      b_e1,      W_e2,          0);
    k_tab<<<NPTS/8, b8>>>(W_e1 + 32, b_e1 + 32, W_e2 + 32*384, NPTS*FF);

    // layer 0 (s1 == 0 -> only j in {0,1,2})
    k_edge<3><<<dim3(NN, NC), 64>>>();
    k_node<true><<<NN/4, b4>>>(nodef, Wp0, Wp1, Wr1, br1, Wr2g, W_lin + 3*FF*FF);

    // layer 1 (j in {0..4}; j==5 multiplies an identically-zero term)
    k_edge<5><<<dim3(NN, NC), 64>>>();
    k_node<false><<<NN/4, b4>>>(nodef, Wp0 + SS*FF*6, Wp1 + SS*FF*3,
                                Wr1 + FF*FF, br1 + FF, Wr2g + FF*FF, nullptr);

    k_out<<<(NN*3 + 255)/256, 256>>>(positions, out);
}

// round 10
// speedup vs baseline: 2.5782x; 1.0090x over previous
#include <cuda_runtime.h>
#include <cuda_fp16.h>
#include <math.h>

#define NN 512
#define FF 64
#define SS 5
#define TT 32
#define NC 8        // sender chunks per receiver
#define CHUNK (NN/NC)
#define TSZ 16      // sender tile size
#define NPTS 4096   // wj table points
#define RMAX 16.0f

// -------- device scratch (no allocations allowed) --------
__device__ float  g_x0v[NN*FF];          // layer0: x0 only
__device__ float4 g_xv[NN*FF];           // layer1: {x0, x1x, x1y, x1z}
__device__ float4 g_tV[2*NPTS*FF];       // table values v0..v3
__device__ uint2  g_tS[2*NPTS*FF];       // slopes s0..s3 as 2x half2
__device__ float2 g_tE[2*NPTS*FF];       // {v4, s4}  (layer1)
__device__ float  g_Apart[NC*NN*9*FF];   // partial segment sums
__device__ float  g_pos[NN*3];           // current positions

// -------- fused embed + layer0 linear (4 nodes / block) --------
__global__ void k_embedlin(const float* __restrict__ pos_in, const int* __restrict__ nodef,
                           const float* __restrict__ te, const float* __restrict__ W_embed,
                           const float* __restrict__ b_embed, const float* __restrict__ Wl0) {
    int ty = threadIdx.y, f = threadIdx.x;
    int n = blockIdx.x*4 + ty;
    __shared__ float sH[4][FF];
    if (f < 3) g_pos[n*3+f] = pos_in[n*3+f];
    int sp = nodef[n] - 1;
    float h = W_embed[sp*FF + f] + b_embed[f];
    #pragma unroll
    for (int t = 0; t < TT; t++) h = fmaf(te[t], W_embed[(SS+t)*FF + f], h);
    sH[ty][f] = h;
    __syncthreads();
    float a0 = 0.f;
    #pragma unroll 8
    for (int g = 0; g < FF; g++) a0 = fmaf(sH[ty][g], Wl0[g*FF + f], a0);
    g_x0v[n*FF + f] = a0;
}

// -------- build wj(r) table (value + slope), 8 points / block --------
__global__ void k_tab(const float* __restrict__ We1, const float* __restrict__ be1,
                      const float* __restrict__ We2, int off) {
    __shared__ float sW[32*320];    // We2 repacked: [k][f*5+j]
    __shared__ float sHe[9][32];
    int f = threadIdx.x, ty = threadIdx.y;
    int tid = ty*64 + f;
    int p0 = blockIdx.x*8;
    const float hstep = RMAX / (float)(NPTS-1);

    for (int idx = tid; idx < 32*320; idx += 512) {
        int k = idx / 320, cc = idx % 320;
        sW[idx] = We2[k*384 + (cc/5)*6 + (cc%5)];
    }
    for (int idx = tid; idx < 9*32; idx += 512) {
        int row = idx >> 5, k = idx & 31;
        int p = p0 + row; if (p > NPTS-1) p = NPTS-1;
        float x = fmaf((float)p * hstep, We1[k], be1[k]);
        sHe[row][k] = x / (1.0f + expf(-x));
    }
    __syncthreads();

    float va[5] = {0,0,0,0,0}, vb[5] = {0,0,0,0,0};
    #pragma unroll 4
    for (int k = 0; k < 32; k++) {
        float hA = sHe[ty][k], hB = sHe[ty+1][k];
        const float* w = &sW[k*320 + f*5];
        #pragma unroll
        for (int j = 0; j < 5; j++) {
            va[j] = fmaf(hA, w[j], va[j]);
            vb[j] = fmaf(hB, w[j], vb[j]);
        }
    }
    int p = p0 + ty;
    int ti = off + p*FF + f;
    g_tV[ti] = make_float4(va[0], va[1], va[2], va[3]);
    __half2 sa = __floats2half2_rn(vb[0]-va[0], vb[1]-va[1]);
    __half2 sb = __floats2half2_rn(vb[2]-va[2], vb[3]-va[3]);
    uint2 su; su.x = *(unsigned*)&sa; su.y = *(unsigned*)&sb;
    g_tS[ti] = su;
    g_tE[ti] = make_float2(va[4], vb[4]-va[4]);
}

// -------- edge kernel: table lookup + message epilogue --------
// NJ = 3 (layer 0, s1==0) or 5 (layer 1).
template<int NJ>
__global__ void __launch_bounds__(64) k_edge() {
    const int r = blockIdx.x, c = blockIdx.y, f = threadIdx.x;
    const int off = (NJ == 5) ? NPTS*FF : 0;
    __shared__ float sY1[TSZ][3];
    __shared__ float sY2[TSZ][5];
    __shared__ int   sIdx[TSZ];
    __shared__ float sFrac[TSZ];
    __shared__ float sVal[TSZ];

    const float prx = g_pos[r*3+0], pry = g_pos[r*3+1], prz = g_pos[r*3+2];
    const float tscale = (float)(NPTS-1) / RMAX;

    float acc[9];
    #pragma unroll
    for (int ch = 0; ch < 9; ch++) acc[ch] = 0.f;

    const int base = c * CHUNK;
    for (int tile = 0; tile < CHUNK/TSZ; tile++) {
        __syncthreads();
        if (f < TSZ) {
            int s = base + tile*TSZ + f;
            float vx = prx - g_pos[s*3+0];
            float vy = pry - g_pos[s*3+1];
            float vz = prz - g_pos[s*3+2];
            float rl = sqrtf(vx*vx + vy*vy + vz*vz);
            int ok = (s != r);
            float inv = ok ? (1.0f/rl) : 0.0f;
            float ux = vx*inv, uy = vy*inv, uz = vz*inv;
            float t = fminf(rl * tscale, (float)NPTS - 1.001f);
            int i = (int)t;
            sIdx[f]  = i;
            sFrac[f] = t - (float)i;
            sVal[f]  = ok ? 1.0f : 0.0f;
            const float s3  = 1.7320508075688772f;
            const float s5h = 0.5f * 2.2360679774997896f;
            const float s15 = 3.8729833462074170f;
            const float s15h = 0.5f * 3.8729833462074170f;
            sY1[f][0] = s3*ux; sY1[f][1] = s3*uy; sY1[f][2] = s3*uz;
            sY2[f][0] = s15*ux*uy;
            sY2[f][1] = s15*uy*uz;
            sY2[f][2] = s5h*(3.f*uz*uz - 1.f);
            sY2[f][3] = s15*ux*uz;
            sY2[f][4] = s15h*(ux*ux - uy*uy);
        }
        __syncthreads();
        #pragma unroll 4
        for (int sl = 0; sl < TSZ; sl++) {
            int s = base + tile*TSZ + sl;
            int i = sIdx[sl];
            float fr = sFrac[sl], val = sVal[sl];
            int ti = off + i*FF + f;

            float4 V = g_tV[ti];
            uint2 Su = g_tS[ti];
            float2 s01 = __half22float2(*(__half2*)&Su.x);
            float2 s23 = __half22float2(*(__half2*)&Su.y);
            float wj0 = fmaf(fr, s01.x, V.x);
            float wj1 = fmaf(fr, s01.y, V.y);
            float wj2 = fmaf(fr, s23.x, V.z);

            float a0v, a1x = 0.f, a1y = 0.f, a1z = 0.f, wj3 = 0.f, wj4 = 0.f;
            if (NJ > 3) {
                wj3 = fmaf(fr, s23.y, V.w);
                float2 E = g_tE[ti];
                wj4 = fmaf(fr, E.y, E.x);
                float4 xv = g_xv[s*FF + f];
                a0v = xv.x * val;
                a1x = xv.y * val; a1y = xv.z * val; a1z = xv.w * val;
            } else {
                a0v = g_x0v[s*FF + f] * val;
            }

            float Y1x = sY1[sl][0], Y1y = sY1[sl][1], Y1z = sY1[sl][2];
            acc[0] = fmaf(wj0, a0v, acc[0]);
            float w1a = wj1 * a0v;
            acc[1] = fmaf(w1a, Y1x, acc[1]);
            acc[2] = fmaf(w1a, Y1y, acc[2]);
            acc[3] = fmaf(w1a, Y1z, acc[3]);
            float w2a = wj2 * a0v;
            acc[4] = fmaf(w2a, sY2[sl][0], acc[4]);
            acc[5] = fmaf(w2a, sY2[sl][1], acc[5]);
            acc[6] = fmaf(w2a, sY2[sl][2], acc[6]);
            acc[7] = fmaf(w2a, sY2[sl][3], acc[7]);
            acc[8] = fmaf(w2a, sY2[sl][4], acc[8]);
            if (NJ > 3) {
                float d1 = a1x*Y1x + a1y*Y1y + a1z*Y1z;
                acc[0] = fmaf(wj3, d1, acc[0]);
                float crx = a1y*Y1z - a1z*Y1y;
                float cry = a1z*Y1x - a1x*Y1z;
                float crz = a1x*Y1y - a1y*Y1x;
                acc[1] = fmaf(wj4, crx, acc[1]);
                acc[2] = fmaf(wj4, cry, acc[2]);
                acc[3] = fmaf(wj4, crz, acc[3]);
            }
        }
    }
    #pragma unroll
    for (int ch = 0; ch < 9; ch++)
        g_Apart[((c*NN + r)*9 + ch)*FF + f] = acc[ch];
}

// -------- node update (4 nodes / block) --------
template<bool DO_LIN>
__global__ void k_node(const int* __restrict__ nodef,
                       const float* __restrict__ Wp0, const float* __restrict__ Wp1,
                       const float* __restrict__ Wr1, const float* __restrict__ br1,
                       const float* __restrict__ Wr2g, const float* __restrict__ WlinNext) {
    int ty = threadIdx.y, f = threadIdx.x;
    int n = blockIdx.x*4 + ty;
    float A[9];
    #pragma unroll
    for (int ch = 0; ch < 9; ch++) {
        float s = 0.f;
        #pragma unroll
        for (int c = 0; c < NC; c++) s += g_Apart[((c*NN + n)*9 + ch)*FF + f];
        A[ch] = s / 511.0f;
    }
    float A0 = A[0];
    float n1 = A[1]*A[1] + A[2]*A[2] + A[3]*A[3];
    float n2 = A[4]*A[4] + A[5]*A[5] + A[6]*A[6] + A[7]*A[7] + A[8]*A[8];
    int sp = nodef[n] - 1;
    const float* w0 = Wp0 + (sp*FF + f)*6;
    float A02 = A0*A0;
    float out0 = w0[0]*A0 + w0[1]*A02 + w0[2]*A02*A0 + w0[3]*n1 + w0[4]*n2 + w0[5]*A0*n1;
    const float* w1 = Wp1 + (sp*FF + f)*3;
    float gp = w1[0] + w1[1]*A0 + w1[2]*A02;
    float o1x = gp*A[1], o1y = gp*A[2], o1z = gp*A[3];

    __shared__ float sO[4][FF];
    __shared__ float sV[4][3][FF];
    sO[ty][f] = out0;
    sV[ty][0][f] = o1x; sV[ty][1][f] = o1y; sV[ty][2][f] = o1z;
    __syncthreads();

    if (DO_LIN) {
        float a0 = 0.f, a1x = 0.f, a1y = 0.f, a1z = 0.f;
        #pragma unroll 8
        for (int g = 0; g < FF; g++) {
            float wa = WlinNext[g*FF + f];
            float wb = WlinNext[FF*FF + g*FF + f];
            a0  = fmaf(sO[ty][g],    wa, a0);
            a1x = fmaf(sV[ty][0][g], wb, a1x);
            a1y = fmaf(sV[ty][1][g], wb, a1y);
            a1z = fmaf(sV[ty][2][g], wb, a1z);
        }
        g_xv[n*FF + f] = make_float4(a0, a1x, a1y, a1z);
    }

    float hx = br1[f];
    #pragma unroll 8
    for (int g = 0; g < FF; g++) hx = fmaf(sO[ty][g], Wr1[g*FF + f], hx);
    float hr = hx / (1.0f + expf(-hx));
    __shared__ float sH[4][FF];
    sH[ty][f] = hr;
    __syncthreads();
    float gate = 0.f;
    #pragma unroll 8
    for (int m = 0; m < FF; m++) gate = fmaf(sH[ty][m], Wr2g[m*FF + f], gate);

    __shared__ float sRed[4][3][FF];
    sRed[ty][0][f] = gate*o1x; sRed[ty][1][f] = gate*o1y; sRed[ty][2][f] = gate*o1z;
    __syncthreads();
    if (f < 3) {
        float v = 0.f;
        for (int g = 0; g < FF; g++) v += sRed[ty][f][g];
        g_pos[n*3 + f] += v;   // deterministic: one thread per component
    }
}

__global__ void k_out(const float* __restrict__ pos_in, float* __restrict__ out) {
    int i = blockIdx.x*blockDim.x + threadIdx.x;
    if (i < NN*3) out[i] = g_pos[i] - pos_in[i];
}

extern "C" void kernel_launch(void* const* d_in, const int* in_sizes, int n_in,
                              void* d_out, int out_size) {
    const float* positions = (const float*)d_in[0];
    const int*   nodef     = (const int*)  d_in[1];
    const float* te        = (const float*)d_in[2];
    // d_in[3]/[4] = senders/receivers: fully connected, structure used directly
    const float* W_embed   = (const float*)d_in[5];
    const float* b_embed   = (const float*)d_in[6];
    const float* W_lin     = (const float*)d_in[7];
    const float* W_e1      = (const float*)d_in[8];
    const float* b_e1      = (const float*)d_in[9];
    const float* W_e2      = (const float*)d_in[10];
    const float* Wp0       = (const float*)d_in[11];
    const float* Wp1       = (const float*)d_in[12];
    const float* Wr1       = (const float*)d_in[13];
    const float* br1       = (const float*)d_in[14];
    // d_in[15] = Wr2s: unused by the reference
    const float* Wr2g      = (const float*)d_in[16];
    float* out = (float*)d_out;

    dim3 b4(64, 4), b8(64, 8);

    k_embedlin<<<NN/4, b4>>>(positions, nodef, te, W_embed, b_embed, W_lin);
    // both tables up front (independent of edges)
    k_tab<<<NPTS/8, b8>>>(W_e1,      b_e1,      W_e2,          0);
    k_tab<<<NPTS/8, b8>>>(W_e1 + 32, b_e1 + 32, W_e2 + 32*384, NPTS*FF);

    // layer 0 (s1 == 0 -> only j in {0,1,2})
    k_edge<3><<<dim3(NN, NC), 64>>>();
    k_node<true><<<NN/4, b4>>>(nodef, Wp0, Wp1, Wr1, br1, Wr2g, W_lin + 3*FF*FF);

    // layer 1 (j in {0..4}; j==5 multiplies an identically-zero term)
    k_edge<5><<<dim3(NN, NC), 64>>>();
    k_node<false><<<NN/4, b4>>>(nodef, Wp0 + SS*FF*6, Wp1 + SS*FF*3,
                                Wr1 + FF*FF, br1 + FF, Wr2g + FF*FF, nullptr);

    k_out<<<(NN*3 + 255)/256, 256>>>(positions, out);
}

// round 11
// speedup vs baseline: 3.1156x; 1.2085x over previous
#include <cuda_runtime.h>
#include <cuda_fp16.h>
#include <math.h>

#define NN 512
#define FF 64
#define SS 5
#define TT 32
#define NC 16       // sender chunks per receiver
#define CHUNK (NN/NC)
#define TSZ 16      // sender tile size
#define NPTS 2048   // wj table points
#define RMAX 16.0f

// -------- device scratch (no allocations allowed) --------
__device__ float  g_x0v[NN*FF];          // layer0: x0 only
__device__ float4 g_xv[NN*FF];           // layer1: {x0, x1x, x1y, x1z}
__device__ float4 g_t0a[NPTS*FF];        // L0 table: {v0,v1,v2, h2(s0,s1)}
__device__ __half g_t0s2[NPTS*FF];       // L0 table: s2
__device__ float4 g_t5a[NPTS*FF];        // L1 table: {v0,v1,v2,v3}
__device__ float4 g_t5b[NPTS*FF];        // L1 table: {v4, h2(s0,s1), h2(s2,s3), h2(s4,0)}
__device__ float  g_Apart[NC*NN*9*FF];   // partial segment sums
__device__ float  g_pos[NN*3];           // current positions

__device__ __forceinline__ float2 h2f(float bits) {
    __half2 h; unsigned u = __float_as_uint(bits);
    h = *(__half2*)&u;
    return __half22float2(h);
}
__device__ __forceinline__ float packh2(float a, float b) {
    __half2 h = __floats2half2_rn(a, b);
    return __uint_as_float(*(unsigned*)&h);
}

// -------- fused embed + layer0 linear (4 nodes / block) --------
__global__ void k_embedlin(const float* __restrict__ pos_in, const int* __restrict__ nodef,
                           const float* __restrict__ te, const float* __restrict__ W_embed,
                           const float* __restrict__ b_embed, const float* __restrict__ Wl0) {
    int ty = threadIdx.y, f = threadIdx.x;
    int n = blockIdx.x*4 + ty;
    __shared__ float sH[4][FF];
    if (f < 3) g_pos[n*3+f] = pos_in[n*3+f];
    int sp = nodef[n] - 1;
    float h = W_embed[sp*FF + f] + b_embed[f];
    #pragma unroll
    for (int t = 0; t < TT; t++) h = fmaf(te[t], W_embed[(SS+t)*FF + f], h);
    sH[ty][f] = h;
    __syncthreads();
    float a0 = 0.f;
    #pragma unroll 8
    for (int g = 0; g < FF; g++) a0 = fmaf(sH[ty][g], Wl0[g*FF + f], a0);
    g_x0v[n*FF + f] = a0;
}

// -------- build wj(r) tables for BOTH layers (blockIdx.y = layer) --------
__global__ void k_tab(const float* __restrict__ We1, const float* __restrict__ be1,
                      const float* __restrict__ We2) {
    __shared__ float sW[32*320];    // We2 repacked: [k][f*5+j]
    __shared__ float sHe[9][32];
    int f = threadIdx.x, ty = threadIdx.y;
    int layer = blockIdx.y;
    int tid = ty*64 + f;
    int p0 = blockIdx.x*8;
    const float hstep = RMAX / (float)(NPTS-1);
    const float* We2l = We2 + layer*32*384;
    const float* We1l = We1 + layer*32;
    const float* be1l = be1 + layer*32;

    for (int idx = tid; idx < 32*320; idx += 512) {
        int k = idx / 320, cc = idx % 320;
        sW[idx] = We2l[k*384 + (cc/5)*6 + (cc%5)];
    }
    for (int idx = tid; idx < 9*32; idx += 512) {
        int row = idx >> 5, k = idx & 31;
        int p = p0 + row; if (p > NPTS-1) p = NPTS-1;
        float x = fmaf((float)p * hstep, We1l[k], be1l[k]);
        sHe[row][k] = x / (1.0f + expf(-x));
    }
    __syncthreads();

    float va[5] = {0,0,0,0,0}, vb[5] = {0,0,0,0,0};
    #pragma unroll 4
    for (int k = 0; k < 32; k++) {
        float hA = sHe[ty][k], hB = sHe[ty+1][k];
        const float* w = &sW[k*320 + f*5];
        #pragma unroll
        for (int j = 0; j < 5; j++) {
            va[j] = fmaf(hA, w[j], va[j]);
            vb[j] = fmaf(hB, w[j], vb[j]);
        }
    }
    int ti = (p0 + ty)*FF + f;
    if (layer == 0) {
        g_t0a[ti] = make_float4(va[0], va[1], va[2],
                                packh2(vb[0]-va[0], vb[1]-va[1]));
        g_t0s2[ti] = __float2half(vb[2]-va[2]);
    } else {
        g_t5a[ti] = make_float4(va[0], va[1], va[2], va[3]);
        g_t5b[ti] = make_float4(va[4],
                                packh2(vb[0]-va[0], vb[1]-va[1]),
                                packh2(vb[2]-va[2], vb[3]-va[3]),
                                packh2(vb[4]-va[4], 0.f));
    }
}

// -------- edge kernel: table lookup + message epilogue --------
template<int NJ>
__global__ void __launch_bounds__(64) k_edge() {
    const int r = blockIdx.x, c = blockIdx.y, f = threadIdx.x;
    __shared__ float sY1[TSZ][3];
    __shared__ float sY2[TSZ][5];
    __shared__ int   sIdx[TSZ];
    __shared__ float sFrac[TSZ];
    __shared__ float sVal[TSZ];

    const float prx = g_pos[r*3+0], pry = g_pos[r*3+1], prz = g_pos[r*3+2];
    const float tscale = (float)(NPTS-1) / RMAX;

    float acc[9];
    #pragma unroll
    for (int ch = 0; ch < 9; ch++) acc[ch] = 0.f;

    const int base = c * CHUNK;
    for (int tile = 0; tile < CHUNK/TSZ; tile++) {
        __syncthreads();
        if (f < TSZ) {
            int s = base + tile*TSZ + f;
            float vx = prx - g_pos[s*3+0];
            float vy = pry - g_pos[s*3+1];
            float vz = prz - g_pos[s*3+2];
            float rl = sqrtf(vx*vx + vy*vy + vz*vz);
            int ok = (s != r);
            float inv = ok ? (1.0f/rl) : 0.0f;
            float ux = vx*inv, uy = vy*inv, uz = vz*inv;
            float t = fminf(rl * tscale, (float)NPTS - 1.001f);
            int i = (int)t;
            sIdx[f]  = i;
            sFrac[f] = t - (float)i;
            sVal[f]  = ok ? 1.0f : 0.0f;
            const float s3  = 1.7320508075688772f;
            const float s5h = 0.5f * 2.2360679774997896f;
            const float s15 = 3.8729833462074170f;
            const float s15h = 0.5f * 3.8729833462074170f;
            sY1[f][0] = s3*ux; sY1[f][1] = s3*uy; sY1[f][2] = s3*uz;
            sY2[f][0] = s15*ux*uy;
            sY2[f][1] = s15*uy*uz;
            sY2[f][2] = s5h*(3.f*uz*uz - 1.f);
            sY2[f][3] = s15*ux*uz;
            sY2[f][4] = s15h*(ux*ux - uy*uy);
        }
        __syncthreads();
        #pragma unroll 4
        for (int sl = 0; sl < TSZ; sl++) {
            int s = base + tile*TSZ + sl;
            int i = sIdx[sl];
            float fr = sFrac[sl], val = sVal[sl];
            int ti = i*FF + f;

            float wj0, wj1, wj2, wj3 = 0.f, wj4 = 0.f;
            float a0v, a1x = 0.f, a1y = 0.f, a1z = 0.f;
            if (NJ > 3) {
                float4 A = g_t5a[ti];
                float4 B = g_t5b[ti];
                float2 s01 = h2f(B.y);
                float2 s23 = h2f(B.z);
                float2 s4p = h2f(B.w);
                wj0 = fmaf(fr, s01.x, A.x);
                wj1 = fmaf(fr, s01.y, A.y);
                wj2 = fmaf(fr, s23.x, A.z);
                wj3 = fmaf(fr, s23.y, A.w);
                wj4 = fmaf(fr, s4p.x, B.x);
                float4 xv = g_xv[s*FF + f];
                a0v = xv.x * val;
                a1x = xv.y * val; a1y = xv.z * val; a1z = xv.w * val;
            } else {
                float4 A = g_t0a[ti];
                float2 s01 = h2f(A.w);
                float s2 = __half2float(g_t0s2[ti]);
                wj0 = fmaf(fr, s01.x, A.x);
                wj1 = fmaf(fr, s01.y, A.y);
                wj2 = fmaf(fr, s2,    A.z);
                a0v = g_x0v[s*FF + f] * val;
            }

            float Y1x = sY1[sl][0], Y1y = sY1[sl][1], Y1z = sY1[sl][2];
            acc[0] = fmaf(wj0, a0v, acc[0]);
            float w1a = wj1 * a0v;
            acc[1] = fmaf(w1a, Y1x, acc[1]);
            acc[2] = fmaf(w1a, Y1y, acc[2]);
            acc[3] = fmaf(w1a, Y1z, acc[3]);
            float w2a = wj2 * a0v;
            acc[4] = fmaf(w2a, sY2[sl][0], acc[4]);
            acc[5] = fmaf(w2a, sY2[sl][1], acc[5]);
            acc[6] = fmaf(w2a, sY2[sl][2], acc[6]);
            acc[7] = fmaf(w2a, sY2[sl][3], acc[7]);
            acc[8] = fmaf(w2a, sY2[sl][4], acc[8]);
            if (NJ > 3) {
                float d1 = a1x*Y1x + a1y*Y1y + a1z*Y1z;
                acc[0] = fmaf(wj3, d1, acc[0]);
                float crx = a1y*Y1z - a1z*Y1y;
                float cry = a1z*Y1x - a1x*Y1z;
                float crz = a1x*Y1y - a1y*Y1x;
                acc[1] = fmaf(wj4, crx, acc[1]);
                acc[2] = fmaf(wj4, cry, acc[2]);
                acc[3] = fmaf(wj4, crz, acc[3]);
            }
        }
    }
    #pragma unroll
    for (int ch = 0; ch < 9; ch++)
        g_Apart[((c*NN + r)*9 + ch)*FF + f] = acc[ch];
}

// -------- node update (4 nodes / block) --------
template<bool DO_LIN>
__global__ void k_node(const int* __restrict__ nodef,
                       const float* __restrict__ Wp0, const float* __restrict__ Wp1,
                       const float* __restrict__ Wr1, const float* __restrict__ br1,
                       const float* __restrict__ Wr2g, const float* __restrict__ WlinNext) {
    int ty = threadIdx.y, f = threadIdx.x;
    int n = blockIdx.x*4 + ty;
    float A[9];
    #pragma unroll
    for (int ch = 0; ch < 9; ch++) {
        float s = 0.f;
        #pragma unroll
        for (int c = 0; c < NC; c++) s += g_Apart[((c*NN + n)*9 + ch)*FF + f];
        A[ch] = s / 511.0f;
    }
    float A0 = A[0];
    float n1 = A[1]*A[1] + A[2]*A[2] + A[3]*A[3];
    float n2 = A[4]*A[4] + A[5]*A[5] + A[6]*A[6] + A[7]*A[7] + A[8]*A[8];
    int sp = nodef[n] - 1;
    const float* w0 = Wp0 + (sp*FF + f)*6;
    float A02 = A0*A0;
    float out0 = w0[0]*A0 + w0[1]*A02 + w0[2]*A02*A0 + w0[3]*n1 + w0[4]*n2 + w0[5]*A0*n1;
    const float* w1 = Wp1 + (sp*FF + f)*3;
    float gp = w1[0] + w1[1]*A0 + w1[2]*A02;
    float o1x = gp*A[1], o1y = gp*A[2], o1z = gp*A[3];

    __shared__ float sO[4][FF];
    __shared__ float sV[4][3][FF];
    sO[ty][f] = out0;
    sV[ty][0][f] = o1x; sV[ty][1][f] = o1y; sV[ty][2][f] = o1z;
    __syncthreads();

    if (DO_LIN) {
        float a0 = 0.f, a1x = 0.f, a1y = 0.f, a1z = 0.f;
        #pragma unroll 8
        for (int g = 0; g < FF; g++) {
            float wa = WlinNext[g*FF + f];
            float wb = WlinNext[FF*FF + g*FF + f];
            a0  = fmaf(sO[ty][g],    wa, a0);
            a1x = fmaf(sV[ty][0][g], wb, a1x);
            a1y = fmaf(sV[ty][1][g], wb, a1y);
            a1z = fmaf(sV[ty][2][g], wb, a1z);
        }
        g_xv[n*FF + f] = make_float4(a0, a1x, a1y, a1z);
    }

    float hx = br1[f];
    #pragma unroll 8
    for (int g = 0; g < FF; g++) hx = fmaf(sO[ty][g], Wr1[g*FF + f], hx);
    float hr = hx / (1.0f + expf(-hx));
    __shared__ float sH[4][FF];
    sH[ty][f] = hr;
    __syncthreads();
    float gate = 0.f;
    #pragma unroll 8
    for (int m = 0; m < FF; m++) gate = fmaf(sH[ty][m], Wr2g[m*FF + f], gate);

    __shared__ float sRed[4][3][FF];
    sRed[ty][0][f] = gate*o1x; sRed[ty][1][f] = gate*o1y; sRed[ty][2][f] = gate*o1z;
    __syncthreads();
    if (f < 3) {
        float v = 0.f;
        for (int g = 0; g < FF; g++) v += sRed[ty][f][g];
        g_pos[n*3 + f] += v;   // deterministic: one thread per component
    }
}

__global__ void k_out(const float* __restrict__ pos_in, float* __restrict__ out) {
    int i = blockIdx.x*blockDim.x + threadIdx.x;
    if (i < NN*3) out[i] = g_pos[i] - pos_in[i];
}

extern "C" void kernel_launch(void* const* d_in, const int* in_sizes, int n_in,
                              void* d_out, int out_size) {
    const float* positions = (const float*)d_in[0];
    const int*   nodef     = (const int*)  d_in[1];
    const float* te        = (const float*)d_in[2];
    // d_in[3]/[4] = senders/receivers: fully connected, structure used directly
    const float* W_embed   = (const float*)d_in[5];
    const float* b_embed   = (const float*)d_in[6];
    const float* W_lin     = (const float*)d_in[7];
    const float* W_e1      = (const float*)d_in[8];
    const float* b_e1      = (const float*)d_in[9];
    const float* W_e2      = (const float*)d_in[10];
    const float* Wp0       = (const float*)d_in[11];
    const float* Wp1       = (const float*)d_in[12];
    const float* Wr1       = (const float*)d_in[13];
    const float* br1       = (const float*)d_in[14];
    // d_in[15] = Wr2s: unused by the reference
    const float* Wr2g      = (const float*)d_in[16];
    float* out = (float*)d_out;

    dim3 b4(64, 4), b8(64, 8);

    // both wj tables in one launch (blockIdx.y = layer)
    k_tab<<<dim3(NPTS/8, 2), b8>>>(W_e1, b_e1, W_e2);
    k_embedlin<<<NN/4, b4>>>(positions, nodef, te, W_embed, b_embed, W_lin);

    // layer 0 (s1 == 0 -> only j in {0,1,2})
    k_edge<3><<<dim3(NN, NC), 64>>>();
    k_node<true><<<NN/4, b4>>>(nodef, Wp0, Wp1, Wr1, br1, Wr2g, W_lin + 3*FF*FF);

    // layer 1 (j in {0..4}; j==5 multiplies an identically-zero term)
    k_edge<5><<<dim3(NN, NC), 64>>>();
    k_node<false><<<NN/4, b4>>>(nodef, Wp0 + SS*FF*6, Wp1 + SS*FF*3,
                                Wr1 + FF*FF, br1 + FF, Wr2g + FF*FF, nullptr);

    k_out<<<(NN*3 + 255)/256, 256>>>(positions, out);
}